// round 3
// baseline (speedup 1.0000x reference)
#include <cuda_runtime.h>

#define NB       262144
#define ZDIM     128
#define ZH       64
#define HS       50
#define HSP      52          // HS padded to 52 (16B-aligned rows, zero pad)
#define NSTAGE   4
#define NTHREADS 256

// SMEM layout (float offsets)
#define W0T_OFF  0                                  // [stage][k=64][j=HSP]  (transposed W_in)
#define WMU_OFF  (NSTAGE*ZH*HSP)                    // [stage][o=64][j=HSP]
#define WSIG_OFF (2*NSTAGE*ZH*HSP)                  // [stage][o=64][j=HSP]
#define BIN_OFF  (3*NSTAGE*ZH*HSP)                  // [stage][HSP]
#define BMU_OFF  (BIN_OFF + NSTAGE*HSP)             // [stage][64]
#define BSIG_OFF (BMU_OFF + NSTAGE*ZH)              // [stage][64]
#define SMEM_FLOATS (BSIG_OFF + NSTAGE*ZH)          // 40656
#define SMEM_BYTES  (SMEM_FLOATS*4)                 // 162624

typedef unsigned long long ull;

__device__ __forceinline__ ull pack2(float lo, float hi) {
    ull r; asm("mov.b64 %0,{%1,%2};" : "=l"(r) : "f"(lo), "f"(hi)); return r;
}
__device__ __forceinline__ void unpack2(ull v, float &lo, float &hi) {
    asm("mov.b64 {%0,%1},%2;" : "=f"(lo), "=f"(hi) : "l"(v));
}
// packed dual-fp32 FMA: d = a*b + d (per 32-bit lane)
__device__ __forceinline__ void fma2(ull &d, ull a, ull b) {
    asm("fma.rn.f32x2 %0,%1,%2,%0;" : "+l"(d) : "l"(a), "l"(b));
}

// One coupling half-step: h = tanh(zin @ W0^T + b0); mu = h@W1^T+b1;
// sig = sigmoid(h@W2^T+b2); zout = zout*sig + mu; logdet += sum(log sig)
__device__ __forceinline__ void coupling(
    const float (&zin)[ZH], float (&zout)[ZH],
    const float* __restrict__ w0t, const float* __restrict__ wmu,
    const float* __restrict__ wsig, const float* __restrict__ bin,
    const float* __restrict__ bmu,  const float* __restrict__ bsig,
    float &logdet)
{
    ull h2[HSP/2];
    const ull* b2 = (const ull*)bin;                 // 8B-aligned (offsets mult. of 208B)
#pragma unroll
    for (int p = 0; p < HSP/2; p++) h2[p] = b2[p];

    // h accumulation, outer-product form: broadcast zin[k], sweep j (paired)
#pragma unroll
    for (int k = 0; k < ZH; k++) {
        ull zz = pack2(zin[k], zin[k]);
        const ulonglong2* wr = (const ulonglong2*)(w0t + k*HSP);  // 16B-aligned rows
#pragma unroll
        for (int p = 0; p < HSP/4; p++) {
            ulonglong2 w = wr[p];
            fma2(h2[2*p + 0], zz, w.x);
            fma2(h2[2*p + 1], zz, w.y);
        }
    }
#pragma unroll
    for (int p = 0; p < HSP/2; p++) {
        float a, b; unpack2(h2[p], a, b);
        h2[p] = pack2(tanhf(a), tanhf(b));           // pad lanes: tanh(0)=0, weights 0
    }

    // mu / sig per output, inner-product form with 4 independent f32x2 accumulators
#pragma unroll
    for (int o = 0; o < ZH; o++) {
        ull am0 = 0ull, am1 = 0ull, as0 = 0ull, as1 = 0ull;
        const ulonglong2* wm = (const ulonglong2*)(wmu  + o*HSP);
        const ulonglong2* ws = (const ulonglong2*)(wsig + o*HSP);
#pragma unroll
        for (int p = 0; p < HSP/4; p++) {
            ulonglong2 a = wm[p];
            fma2(am0, h2[2*p + 0], a.x);
            fma2(am1, h2[2*p + 1], a.y);
            ulonglong2 b = ws[p];
            fma2(as0, h2[2*p + 0], b.x);
            fma2(as1, h2[2*p + 1], b.y);
        }
        float m0,m1,m2,m3, s0,s1,s2,s3;
        unpack2(am0, m0, m1); unpack2(am1, m2, m3);
        unpack2(as0, s0, s1); unpack2(as1, s2, s3);
        float mu = bmu[o]  + ((m0 + m1) + (m2 + m3));
        float t  = bsig[o] + ((s0 + s1) + (s2 + s3));
        float e  = __expf(-t);
        float sig = 1.0f / (1.0f + e);
        zout[o] = zout[o] * sig + mu;
        logdet -= log1pf(e);                         // log(sigmoid(t)) = -log1p(e^-t)
    }
}

__global__ void __launch_bounds__(NTHREADS, 1) flow_kernel(
    const float* __restrict__ g_mean, const float* __restrict__ g_logvar,
    const float* __restrict__ g_eps,
    const float* __restrict__ g_Win,  const float* __restrict__ g_bin,
    const float* __restrict__ g_Wmu,  const float* __restrict__ g_bmu,
    const float* __restrict__ g_Wsig, const float* __restrict__ g_bsig,
    float* __restrict__ g_out)
{
    extern __shared__ float sm[];
    const int tid = threadIdx.x;

    // zero (covers the j-padding lanes), then stage all weights in SMEM
    for (int i = tid; i < SMEM_FLOATS; i += NTHREADS) sm[i] = 0.f;
    __syncthreads();
    for (int i = tid; i < NSTAGE*HS*ZH; i += NTHREADS) {   // W_in, transposed -> [s][k][j]
        int s = i / (HS*ZH); int r = i - s*(HS*ZH);
        int j = r / ZH;      int k = r - j*ZH;
        sm[W0T_OFF + (s*ZH + k)*HSP + j] = g_Win[i];
    }
    for (int i = tid; i < NSTAGE*ZH*HS; i += NTHREADS) {   // W_mu / W_sig -> [s][o][j]
        int s = i / (ZH*HS); int r = i - s*(ZH*HS);
        int o = r / HS;      int j = r - o*HS;
        sm[WMU_OFF  + (s*ZH + o)*HSP + j] = g_Wmu[i];
        sm[WSIG_OFF + (s*ZH + o)*HSP + j] = g_Wsig[i];
    }
    for (int i = tid; i < NSTAGE*HS; i += NTHREADS) {
        int s = i / HS; int j = i - s*HS;
        sm[BIN_OFF + s*HSP + j] = g_bin[i];
    }
    for (int i = tid; i < NSTAGE*ZH; i += NTHREADS) {
        sm[BMU_OFF  + i] = g_bmu[i];
        sm[BSIG_OFF + i] = g_bsig[i];
    }
    __syncthreads();

    const int row = blockIdx.x * NTHREADS + tid;
    const float4* m4 = (const float4*)(g_mean   + (size_t)row * ZDIM);
    const float4* l4 = (const float4*)(g_logvar + (size_t)row * ZDIM);
    const float4* e4 = (const float4*)(g_eps    + (size_t)row * ZDIM);

    float z1[ZH], z2[ZH];
    float slv = 0.f, se2 = 0.f;
#pragma unroll
    for (int i = 0; i < ZH/4; i++) {
        float4 m = m4[i], l = l4[i], e = e4[i];
        z1[4*i+0] = e.x * __expf(0.5f*l.x) + m.x;
        z1[4*i+1] = e.y * __expf(0.5f*l.y) + m.y;
        z1[4*i+2] = e.z * __expf(0.5f*l.z) + m.z;
        z1[4*i+3] = e.w * __expf(0.5f*l.w) + m.w;
        slv += (l.x + l.y) + (l.z + l.w);
        se2 += (e.x*e.x + e.y*e.y) + (e.z*e.z + e.w*e.w);
    }
#pragma unroll
    for (int i = 0; i < ZH/4; i++) {
        float4 m = m4[ZH/4 + i], l = l4[ZH/4 + i], e = e4[ZH/4 + i];
        z2[4*i+0] = e.x * __expf(0.5f*l.x) + m.x;
        z2[4*i+1] = e.y * __expf(0.5f*l.y) + m.y;
        z2[4*i+2] = e.z * __expf(0.5f*l.z) + m.z;
        z2[4*i+3] = e.w * __expf(0.5f*l.w) + m.w;
        slv += (l.x + l.y) + (l.z + l.w);
        se2 += (e.x*e.x + e.y*e.y) + (e.z*e.z + e.w*e.w);
    }
    // (z-mean)^2/exp(logvar) == eps^2 exactly
    const float logqz0 = -0.5f * (slv + se2);
    float logdet = 0.f;

#pragma unroll 1   // keep rolled: bounds I-cache footprint to 2 coupling bodies
    for (int f = 0; f < 2; f++) {
        {
            const int s = 2*f;
            coupling(z1, z2,
                     sm + W0T_OFF + s*ZH*HSP, sm + WMU_OFF + s*ZH*HSP,
                     sm + WSIG_OFF + s*ZH*HSP, sm + BIN_OFF + s*HSP,
                     sm + BMU_OFF + s*ZH, sm + BSIG_OFF + s*ZH, logdet);
        }
        {
            const int s = 2*f + 1;
            coupling(z2, z1,
                     sm + W0T_OFF + s*ZH*HSP, sm + WMU_OFF + s*ZH*HSP,
                     sm + WSIG_OFF + s*ZH*HSP, sm + BIN_OFF + s*HSP,
                     sm + BMU_OFF + s*ZH, sm + BSIG_OFF + s*ZH, logdet);
        }
    }

    // epilogue: z = [z1, z2], logpz = -0.5*sum(z^2), logqz = logqz0 - logdet
    float sq = 0.f;
    float4* o4 = (float4*)(g_out + (size_t)row * ZDIM);
#pragma unroll
    for (int i = 0; i < ZH/4; i++) {
        float a = z1[4*i+0], b = z1[4*i+1], c = z1[4*i+2], d = z1[4*i+3];
        o4[i] = make_float4(a, b, c, d);
        sq += (a*a + b*b) + (c*c + d*d);
    }
#pragma unroll
    for (int i = 0; i < ZH/4; i++) {
        float a = z2[4*i+0], b = z2[4*i+1], c = z2[4*i+2], d = z2[4*i+3];
        o4[ZH/4 + i] = make_float4(a, b, c, d);
        sq += (a*a + b*b) + (c*c + d*d);
    }
    g_out[(size_t)NB*ZDIM + row]      = -0.5f * sq;      // logpz
    g_out[(size_t)NB*ZDIM + NB + row] = logqz0 - logdet; // logqz
}

extern "C" void kernel_launch(void* const* d_in, const int* in_sizes, int n_in,
                              void* d_out, int out_size)
{
    (void)in_sizes; (void)n_in; (void)out_size;
    cudaFuncSetAttribute(flow_kernel,
                         cudaFuncAttributeMaxDynamicSharedMemorySize, SMEM_BYTES);
    flow_kernel<<<NB / NTHREADS, NTHREADS, SMEM_BYTES>>>(
        (const float*)d_in[0], (const float*)d_in[1], (const float*)d_in[2],
        (const float*)d_in[3], (const float*)d_in[4], (const float*)d_in[5],
        (const float*)d_in[6], (const float*)d_in[7], (const float*)d_in[8],
        (float*)d_out);
}

// round 4
// speedup vs baseline: 1.5197x; 1.5197x over previous
#include <cuda_runtime.h>

#define NB       262144
#define ZDIM     128
#define ZH       64
#define HS       50
#define HSP      52                     // HS padded to 52 floats (16B rows)
#define NSTAGE   4
#define NTHREADS 384                    // 2 threads per row, 192 rows/CTA
#define GRID     1366                   // ceil(NB*2 / NTHREADS)

// 16B skew between the two 32-row halves of every weight matrix so the two
// broadcast groups (even/odd lanes) hit disjoint banks.
#define HALF_OFF (32*HSP + 4)           // 1668 floats
#define STG_W    (ZH*HSP + 4)           // 3332 floats per stage per matrix

// SMEM layout (float offsets)
#define W0T_OFF  0                       // [s][k][j] transposed W_in, skewed
#define WMU_OFF  (NSTAGE*STG_W)          // [s][o][j] skewed
#define WSIG_OFF (2*NSTAGE*STG_W)
#define BIN_OFF  (3*NSTAGE*STG_W)        // [s][HSP]
#define BMU_OFF  (BIN_OFF + NSTAGE*HSP)  // [s][68] (34 per half, skewed)
#define BSIG_OFF (BMU_OFF + NSTAGE*68)
#define SMEM_FLOATS (BSIG_OFF + NSTAGE*68)   // 40736
#define SMEM_BYTES  (SMEM_FLOATS*4)          // 162944

typedef unsigned long long ull;

__device__ __forceinline__ ull pack2(float lo, float hi) {
    ull r; asm("mov.b64 %0,{%1,%2};" : "=l"(r) : "f"(lo), "f"(hi)); return r;
}
__device__ __forceinline__ void unpack2(ull v, float &lo, float &hi) {
    asm("mov.b64 {%0,%1},%2;" : "=f"(lo), "=f"(hi) : "l"(v));
}
__device__ __forceinline__ void fma2(ull &d, ull a, ull b) {
    asm("fma.rn.f32x2 %0,%1,%2,%0;" : "+l"(d) : "l"(a), "l"(b));
}
__device__ __forceinline__ void add2(ull &d, ull a) {
    asm("add.rn.f32x2 %0,%0,%1;" : "+l"(d) : "l"(a));
}

// One coupling half-step, lane-pair cooperative.
// Thread owns zin[32] (k = half*32+kl), updates zout[32] (o = half*32+ol).
__device__ __forceinline__ void coupling(
    const float (&zin)[32], float (&zout)[32], const int half,
    const float* __restrict__ w0t_s, const float* __restrict__ wmu_s,
    const float* __restrict__ wsig_s, const float* __restrict__ bin_s,
    const float* __restrict__ bmu_s,  const float* __restrict__ bsig_s,
    float &logdet)
{
    ull hp[26];
    {   // bias added once per pair (half 0 only); same addr -> broadcast LDS
        const ull* b2 = (const ull*)bin_s;
#pragma unroll
        for (int p = 0; p < 26; p++) hp[p] = half ? 0ull : b2[p];
    }
    // partial h over own 32 k's (outer-product; zin stays in registers)
    {
        const float* wb = w0t_s + half*HALF_OFF;
#pragma unroll
        for (int k = 0; k < 32; k++) {
            ull zz = pack2(zin[k], zin[k]);
            const ulonglong2* wr = (const ulonglong2*)(wb + k*HSP);
#pragma unroll
            for (int p = 0; p < 13; p++) {
                ulonglong2 w = wr[p];
                fma2(hp[2*p + 0], zz, w.x);
                fma2(hp[2*p + 1], zz, w.y);
            }
        }
    }
    // butterfly-reduce partial h across the lane pair
#pragma unroll
    for (int p = 0; p < 26; p++) {
        ull o = __shfl_xor_sync(0xffffffffu, hp[p], 1);
        add2(hp[p], o);
    }
    // tanh: split 26/26 across the pair, exchange results
#pragma unroll
    for (int i = 0; i < 13; i++) {
        ull mine = half ? hp[13 + i] : hp[i];
        float x, y; unpack2(mine, x, y);
        ull tt = pack2(tanhf(x), tanhf(y));          // pad lanes: tanh(0)=0
        ull peer = __shfl_xor_sync(0xffffffffu, tt, 1);
        hp[i]      = half ? peer : tt;
        hp[13 + i] = half ? tt   : peer;
    }
    // mu / sig for own 32 outputs
    const float* wm_b = wmu_s  + half*HALF_OFF;
    const float* ws_b = wsig_s + half*HALF_OFF;
    const float* bm_h = bmu_s  + half*34;
    const float* bs_h = bsig_s + half*34;
#pragma unroll
    for (int o = 0; o < 32; o++) {
        ull am0 = 0ull, am1 = 0ull, as0 = 0ull, as1 = 0ull;
        const ulonglong2* wm = (const ulonglong2*)(wm_b + o*HSP);
        const ulonglong2* ws = (const ulonglong2*)(ws_b + o*HSP);
#pragma unroll
        for (int p = 0; p < 13; p++) {
            ulonglong2 a = wm[p];
            fma2(am0, hp[2*p + 0], a.x);
            fma2(am1, hp[2*p + 1], a.y);
            ulonglong2 b = ws[p];
            fma2(as0, hp[2*p + 0], b.x);
            fma2(as1, hp[2*p + 1], b.y);
        }
        float m0,m1,m2,m3, s0,s1,s2,s3;
        unpack2(am0, m0, m1); unpack2(am1, m2, m3);
        unpack2(as0, s0, s1); unpack2(as1, s2, s3);
        float mu = bm_h[o] + ((m0 + m1) + (m2 + m3));
        float t  = bs_h[o] + ((s0 + s1) + (s2 + s3));
        float e  = __expf(-t);
        float sig = 1.0f / (1.0f + e);
        zout[o] = zout[o] * sig + mu;
        logdet -= log1pf(e);                          // log(sigmoid(t))
    }
}

__global__ void __launch_bounds__(NTHREADS, 1) flow_kernel(
    const float* __restrict__ g_mean, const float* __restrict__ g_logvar,
    const float* __restrict__ g_eps,
    const float* __restrict__ g_Win,  const float* __restrict__ g_bin,
    const float* __restrict__ g_Wmu,  const float* __restrict__ g_bmu,
    const float* __restrict__ g_Wsig, const float* __restrict__ g_bsig,
    float* __restrict__ g_out)
{
    extern __shared__ float sm[];
    const int tid = threadIdx.x;

    // zero (covers pads/skew), then stage all weights in SMEM
    for (int i = tid; i < SMEM_FLOATS; i += NTHREADS) sm[i] = 0.f;
    __syncthreads();
    for (int i = tid; i < NSTAGE*HS*ZH; i += NTHREADS) {   // W_in -> [s][k][j], skewed
        int s = i / (HS*ZH); int r = i - s*(HS*ZH);
        int j = r / ZH;      int k = r - j*ZH;
        sm[W0T_OFF + s*STG_W + k*HSP + ((k >= 32) ? 4 : 0) + j] = g_Win[i];
    }
    for (int i = tid; i < NSTAGE*ZH*HS; i += NTHREADS) {   // W_mu/W_sig -> [s][o][j], skewed
        int s = i / (ZH*HS); int r = i - s*(ZH*HS);
        int o = r / HS;      int j = r - o*HS;
        int off = s*STG_W + o*HSP + ((o >= 32) ? 4 : 0) + j;
        sm[WMU_OFF  + off] = g_Wmu[i];
        sm[WSIG_OFF + off] = g_Wsig[i];
    }
    for (int i = tid; i < NSTAGE*HS; i += NTHREADS) {
        int s = i / HS; int j = i - s*HS;
        sm[BIN_OFF + s*HSP + j] = g_bin[i];
    }
    for (int i = tid; i < NSTAGE*ZH; i += NTHREADS) {
        int s = i / ZH; int o = i - s*ZH;
        int oo = (o < 32) ? o : (34 + (o - 32));
        sm[BMU_OFF  + s*68 + oo] = g_bmu[i];
        sm[BSIG_OFF + s*68 + oo] = g_bsig[i];
    }
    __syncthreads();

    const int gt   = blockIdx.x * NTHREADS + tid;
    const int row  = gt >> 1;
    const int half = gt & 1;
    if (row >= NB) return;                 // whole-warp exits only (128 = 4 warps)

    // load own quarter-row pieces: z1 half and z2 half
    const size_t rb = (size_t)row * ZDIM;
    const float4* m1 = (const float4*)(g_mean   + rb + half*32);
    const float4* l1 = (const float4*)(g_logvar + rb + half*32);
    const float4* e1 = (const float4*)(g_eps    + rb + half*32);
    const float4* m2 = (const float4*)(g_mean   + rb + 64 + half*32);
    const float4* l2 = (const float4*)(g_logvar + rb + 64 + half*32);
    const float4* e2 = (const float4*)(g_eps    + rb + 64 + half*32);

    float z1[32], z2[32];
    float slv = 0.f, se2 = 0.f;
#pragma unroll
    for (int i = 0; i < 8; i++) {
        float4 m = m1[i], l = l1[i], e = e1[i];
        z1[4*i+0] = e.x * __expf(0.5f*l.x) + m.x;
        z1[4*i+1] = e.y * __expf(0.5f*l.y) + m.y;
        z1[4*i+2] = e.z * __expf(0.5f*l.z) + m.z;
        z1[4*i+3] = e.w * __expf(0.5f*l.w) + m.w;
        slv += (l.x + l.y) + (l.z + l.w);
        se2 += (e.x*e.x + e.y*e.y) + (e.z*e.z + e.w*e.w);
    }
#pragma unroll
    for (int i = 0; i < 8; i++) {
        float4 m = m2[i], l = l2[i], e = e2[i];
        z2[4*i+0] = e.x * __expf(0.5f*l.x) + m.x;
        z2[4*i+1] = e.y * __expf(0.5f*l.y) + m.y;
        z2[4*i+2] = e.z * __expf(0.5f*l.z) + m.z;
        z2[4*i+3] = e.w * __expf(0.5f*l.w) + m.w;
        slv += (l.x + l.y) + (l.z + l.w);
        se2 += (e.x*e.x + e.y*e.y) + (e.z*e.z + e.w*e.w);
    }
    // (z-mean)^2/exp(logvar) == eps^2 exactly
    float part = slv + se2;                 // per-thread partial of -2*logqz0
    float logdet = 0.f;

#pragma unroll 1   // keep flow loop rolled: bounds I-cache footprint
    for (int f = 0; f < 2; f++) {
        {
            const int s = 2*f;
            coupling(z1, z2, half,
                     sm + W0T_OFF + s*STG_W, sm + WMU_OFF + s*STG_W,
                     sm + WSIG_OFF + s*STG_W, sm + BIN_OFF + s*HSP,
                     sm + BMU_OFF + s*68, sm + BSIG_OFF + s*68, logdet);
        }
        {
            const int s = 2*f + 1;
            coupling(z2, z1, half,
                     sm + W0T_OFF + s*STG_W, sm + WMU_OFF + s*STG_W,
                     sm + WSIG_OFF + s*STG_W, sm + BIN_OFF + s*HSP,
                     sm + BMU_OFF + s*68, sm + BSIG_OFF + s*68, logdet);
        }
    }

    // epilogue: write z, reduce logpz / logqz across the lane pair
    float sq = 0.f;
    float4* o1 = (float4*)(g_out + rb + half*32);
    float4* o2 = (float4*)(g_out + rb + 64 + half*32);
#pragma unroll
    for (int i = 0; i < 8; i++) {
        float a = z1[4*i+0], b = z1[4*i+1], c = z1[4*i+2], d = z1[4*i+3];
        o1[i] = make_float4(a, b, c, d);
        sq += (a*a + b*b) + (c*c + d*d);
    }
#pragma unroll
    for (int i = 0; i < 8; i++) {
        float a = z2[4*i+0], b = z2[4*i+1], c = z2[4*i+2], d = z2[4*i+3];
        o2[i] = make_float4(a, b, c, d);
        sq += (a*a + b*b) + (c*c + d*d);
    }
    sq     += __shfl_xor_sync(0xffffffffu, sq, 1);
    part   += __shfl_xor_sync(0xffffffffu, part, 1);
    logdet += __shfl_xor_sync(0xffffffffu, logdet, 1);
    if (half == 0) {
        g_out[(size_t)NB*ZDIM + row]      = -0.5f * sq;            // logpz
        g_out[(size_t)NB*ZDIM + NB + row] = -0.5f * part - logdet; // logqz
    }
}

extern "C" void kernel_launch(void* const* d_in, const int* in_sizes, int n_in,
                              void* d_out, int out_size)
{
    (void)in_sizes; (void)n_in; (void)out_size;
    cudaFuncSetAttribute(flow_kernel,
                         cudaFuncAttributeMaxDynamicSharedMemorySize, SMEM_BYTES);
    flow_kernel<<<GRID, NTHREADS, SMEM_BYTES>>>(
        (const float*)d_in[0], (const float*)d_in[1], (const float*)d_in[2],
        (const float*)d_in[3], (const float*)d_in[4], (const float*)d_in[5],
        (const float*)d_in[6], (const float*)d_in[7], (const float*)d_in[8],
        (float*)d_out);
}

// round 5
// speedup vs baseline: 1.5230x; 1.0022x over previous
#include <cuda_runtime.h>

#define NB       262144
#define ZDIM     128
#define ZH       64
#define HS       50
#define HSP      52                     // HS padded to 52 floats (16B rows)
#define NSTAGE   4
#define NTHREADS 384                    // 2 threads per row, 192 rows/CTA
#define GRID     1366                   // ceil(NB*2 / NTHREADS)

// 16B skew between the two 32-row halves of every weight matrix so the two
// broadcast groups (even/odd lanes) hit disjoint banks.
#define HALF_OFF (32*HSP + 4)           // 1668 floats
#define STG_W    (ZH*HSP + 4)           // 3332 floats per stage per matrix

// SMEM layout (float offsets)
#define W0T_OFF  0                       // [s][k][j] transposed W_in, skewed
#define WMU_OFF  (NSTAGE*STG_W)          // [s][o][j] skewed
#define WSIG_OFF (2*NSTAGE*STG_W)
#define BIN_OFF  (3*NSTAGE*STG_W)        // [s][HSP]
#define BMU_OFF  (BIN_OFF + NSTAGE*HSP)  // [s][68] (34 per half, skewed)
#define BSIG_OFF (BMU_OFF + NSTAGE*68)
#define SMEM_FLOATS (BSIG_OFF + NSTAGE*68)   // 40736
#define SMEM_BYTES  (SMEM_FLOATS*4)          // 162944

typedef unsigned long long ull;

__device__ __forceinline__ ull pack2(float lo, float hi) {
    ull r; asm("mov.b64 %0,{%1,%2};" : "=l"(r) : "f"(lo), "f"(hi)); return r;
}
__device__ __forceinline__ void unpack2(ull v, float &lo, float &hi) {
    asm("mov.b64 {%0,%1},%2;" : "=f"(lo), "=f"(hi) : "l"(v));
}
__device__ __forceinline__ void fma2(ull &d, ull a, ull b) {
    asm("fma.rn.f32x2 %0,%1,%2,%0;" : "+l"(d) : "l"(a), "l"(b));
}
__device__ __forceinline__ void add2(ull &d, ull a) {
    asm("add.rn.f32x2 %0,%0,%1;" : "+l"(d) : "l"(a));
}

// One coupling half-step, lane-pair cooperative.
// Thread owns zin[32] (k = half*32+kl), updates zout[32] (o = half*32+ol).
__device__ __forceinline__ void coupling(
    const float (&zin)[32], float (&zout)[32], const int half,
    const float* __restrict__ w0t_s, const float* __restrict__ wmu_s,
    const float* __restrict__ wsig_s, const float* __restrict__ bin_s,
    const float* __restrict__ bmu_s,  const float* __restrict__ bsig_s,
    float &logdet)
{
    ull hp[26];
    {   // bias added once per pair (half 0 only); same addr -> broadcast LDS
        const ull* b2 = (const ull*)bin_s;
#pragma unroll
        for (int p = 0; p < 26; p++) hp[p] = half ? 0ull : b2[p];
    }
    // partial h over own 32 k's (outer-product; zin stays in registers)
    {
        const float* wb = w0t_s + half*HALF_OFF;
#pragma unroll
        for (int k = 0; k < 32; k++) {
            ull zz = pack2(zin[k], zin[k]);
            const ulonglong2* wr = (const ulonglong2*)(wb + k*HSP);
#pragma unroll
            for (int p = 0; p < 13; p++) {
                ulonglong2 w = wr[p];
                fma2(hp[2*p + 0], zz, w.x);
                fma2(hp[2*p + 1], zz, w.y);
            }
        }
    }
    // butterfly-reduce partial h across the lane pair
#pragma unroll
    for (int p = 0; p < 26; p++) {
        ull o = __shfl_xor_sync(0xffffffffu, hp[p], 1);
        add2(hp[p], o);
    }
    // tanh: split 26/26 across the pair, exchange results
#pragma unroll
    for (int i = 0; i < 13; i++) {
        ull mine = half ? hp[13 + i] : hp[i];
        float x, y; unpack2(mine, x, y);
        ull tt = pack2(tanhf(x), tanhf(y));          // pad lanes: tanh(0)=0
        ull peer = __shfl_xor_sync(0xffffffffu, tt, 1);
        hp[i]      = half ? peer : tt;
        hp[13 + i] = half ? tt   : peer;
    }
    // mu / sig for own 32 outputs
    const float* wm_b = wmu_s  + half*HALF_OFF;
    const float* ws_b = wsig_s + half*HALF_OFF;
    const float* bm_h = bmu_s  + half*34;
    const float* bs_h = bsig_s + half*34;
#pragma unroll
    for (int o = 0; o < 32; o++) {
        ull am0 = 0ull, am1 = 0ull, as0 = 0ull, as1 = 0ull;
        const ulonglong2* wm = (const ulonglong2*)(wm_b + o*HSP);
        const ulonglong2* ws = (const ulonglong2*)(ws_b + o*HSP);
#pragma unroll
        for (int p = 0; p < 13; p++) {
            ulonglong2 a = wm[p];
            fma2(am0, hp[2*p + 0], a.x);
            fma2(am1, hp[2*p + 1], a.y);
            ulonglong2 b = ws[p];
            fma2(as0, hp[2*p + 0], b.x);
            fma2(as1, hp[2*p + 1], b.y);
        }
        float m0,m1,m2,m3, s0,s1,s2,s3;
        unpack2(am0, m0, m1); unpack2(am1, m2, m3);
        unpack2(as0, s0, s1); unpack2(as1, s2, s3);
        float mu = bm_h[o] + ((m0 + m1) + (m2 + m3));
        float t  = bs_h[o] + ((s0 + s1) + (s2 + s3));
        float e  = __expf(-t);
        float sig = 1.0f / (1.0f + e);
        zout[o] = zout[o] * sig + mu;
        logdet -= log1pf(e);                          // log(sigmoid(t))
    }
}

__global__ void __launch_bounds__(NTHREADS, 1) flow_kernel(
    const float* __restrict__ g_mean, const float* __restrict__ g_logvar,
    const float* __restrict__ g_eps,
    const float* __restrict__ g_Win,  const float* __restrict__ g_bin,
    const float* __restrict__ g_Wmu,  const float* __restrict__ g_bmu,
    const float* __restrict__ g_Wsig, const float* __restrict__ g_bsig,
    float* __restrict__ g_out)
{
    extern __shared__ float sm[];
    const int tid = threadIdx.x;

    // zero (covers pads/skew), then stage all weights in SMEM
    for (int i = tid; i < SMEM_FLOATS; i += NTHREADS) sm[i] = 0.f;
    __syncthreads();
    for (int i = tid; i < NSTAGE*HS*ZH; i += NTHREADS) {   // W_in -> [s][k][j], skewed
        int s = i / (HS*ZH); int r = i - s*(HS*ZH);
        int j = r / ZH;      int k = r - j*ZH;
        sm[W0T_OFF + s*STG_W + k*HSP + ((k >= 32) ? 4 : 0) + j] = g_Win[i];
    }
    for (int i = tid; i < NSTAGE*ZH*HS; i += NTHREADS) {   // W_mu/W_sig -> [s][o][j], skewed
        int s = i / (ZH*HS); int r = i - s*(ZH*HS);
        int o = r / HS;      int j = r - o*HS;
        int off = s*STG_W + o*HSP + ((o >= 32) ? 4 : 0) + j;
        sm[WMU_OFF  + off] = g_Wmu[i];
        sm[WSIG_OFF + off] = g_Wsig[i];
    }
    for (int i = tid; i < NSTAGE*HS; i += NTHREADS) {
        int s = i / HS; int j = i - s*HS;
        sm[BIN_OFF + s*HSP + j] = g_bin[i];
    }
    for (int i = tid; i < NSTAGE*ZH; i += NTHREADS) {
        int s = i / ZH; int o = i - s*ZH;
        int oo = (o < 32) ? o : (34 + (o - 32));
        sm[BMU_OFF  + s*68 + oo] = g_bmu[i];
        sm[BSIG_OFF + s*68 + oo] = g_bsig[i];
    }
    __syncthreads();

    const int gt   = blockIdx.x * NTHREADS + tid;
    const int row  = gt >> 1;
    const int half = gt & 1;
    if (row >= NB) return;                 // whole-warp exits only (128 = 4 warps)

    // load own quarter-row pieces: z1 half and z2 half
    const size_t rb = (size_t)row * ZDIM;
    const float4* m1 = (const float4*)(g_mean   + rb + half*32);
    const float4* l1 = (const float4*)(g_logvar + rb + half*32);
    const float4* e1 = (const float4*)(g_eps    + rb + half*32);
    const float4* m2 = (const float4*)(g_mean   + rb + 64 + half*32);
    const float4* l2 = (const float4*)(g_logvar + rb + 64 + half*32);
    const float4* e2 = (const float4*)(g_eps    + rb + 64 + half*32);

    float z1[32], z2[32];
    float slv = 0.f, se2 = 0.f;
#pragma unroll
    for (int i = 0; i < 8; i++) {
        float4 m = m1[i], l = l1[i], e = e1[i];
        z1[4*i+0] = e.x * __expf(0.5f*l.x) + m.x;
        z1[4*i+1] = e.y * __expf(0.5f*l.y) + m.y;
        z1[4*i+2] = e.z * __expf(0.5f*l.z) + m.z;
        z1[4*i+3] = e.w * __expf(0.5f*l.w) + m.w;
        slv += (l.x + l.y) + (l.z + l.w);
        se2 += (e.x*e.x + e.y*e.y) + (e.z*e.z + e.w*e.w);
    }
#pragma unroll
    for (int i = 0; i < 8; i++) {
        float4 m = m2[i], l = l2[i], e = e2[i];
        z2[4*i+0] = e.x * __expf(0.5f*l.x) + m.x;
        z2[4*i+1] = e.y * __expf(0.5f*l.y) + m.y;
        z2[4*i+2] = e.z * __expf(0.5f*l.z) + m.z;
        z2[4*i+3] = e.w * __expf(0.5f*l.w) + m.w;
        slv += (l.x + l.y) + (l.z + l.w);
        se2 += (e.x*e.x + e.y*e.y) + (e.z*e.z + e.w*e.w);
    }
    // (z-mean)^2/exp(logvar) == eps^2 exactly
    float part = slv + se2;                 // per-thread partial of -2*logqz0
    float logdet = 0.f;

#pragma unroll 1   // keep flow loop rolled: bounds I-cache footprint
    for (int f = 0; f < 2; f++) {
        {
            const int s = 2*f;
            coupling(z1, z2, half,
                     sm + W0T_OFF + s*STG_W, sm + WMU_OFF + s*STG_W,
                     sm + WSIG_OFF + s*STG_W, sm + BIN_OFF + s*HSP,
                     sm + BMU_OFF + s*68, sm + BSIG_OFF + s*68, logdet);
        }
        {
            const int s = 2*f + 1;
            coupling(z2, z1, half,
                     sm + W0T_OFF + s*STG_W, sm + WMU_OFF + s*STG_W,
                     sm + WSIG_OFF + s*STG_W, sm + BIN_OFF + s*HSP,
                     sm + BMU_OFF + s*68, sm + BSIG_OFF + s*68, logdet);
        }
    }

    // epilogue: write z, reduce logpz / logqz across the lane pair
    float sq = 0.f;
    float4* o1 = (float4*)(g_out + rb + half*32);
    float4* o2 = (float4*)(g_out + rb + 64 + half*32);
#pragma unroll
    for (int i = 0; i < 8; i++) {
        float a = z1[4*i+0], b = z1[4*i+1], c = z1[4*i+2], d = z1[4*i+3];
        o1[i] = make_float4(a, b, c, d);
        sq += (a*a + b*b) + (c*c + d*d);
    }
#pragma unroll
    for (int i = 0; i < 8; i++) {
        float a = z2[4*i+0], b = z2[4*i+1], c = z2[4*i+2], d = z2[4*i+3];
        o2[i] = make_float4(a, b, c, d);
        sq += (a*a + b*b) + (c*c + d*d);
    }
    sq     += __shfl_xor_sync(0xffffffffu, sq, 1);
    part   += __shfl_xor_sync(0xffffffffu, part, 1);
    logdet += __shfl_xor_sync(0xffffffffu, logdet, 1);
    if (half == 0) {
        g_out[(size_t)NB*ZDIM + row]      = -0.5f * sq;            // logpz
        g_out[(size_t)NB*ZDIM + NB + row] = -0.5f * part - logdet; // logqz
    }
}

extern "C" void kernel_launch(void* const* d_in, const int* in_sizes, int n_in,
                              void* d_out, int out_size)
{
    (void)in_sizes; (void)n_in; (void)out_size;
    cudaFuncSetAttribute(flow_kernel,
                         cudaFuncAttributeMaxDynamicSharedMemorySize, SMEM_BYTES);
    flow_kernel<<<GRID, NTHREADS, SMEM_BYTES>>>(
        (const float*)d_in[0], (const float*)d_in[1], (const float*)d_in[2],
        (const float*)d_in[3], (const float*)d_in[4], (const float*)d_in[5],
        (const float*)d_in[6], (const float*)d_in[7], (const float*)d_in[8],
        (float*)d_out);
}